// round 1
// baseline (speedup 1.0000x reference)
#include <cuda_runtime.h>

#define NUM_EMB 1024
#define EMB_DIM 64
#define NPIX    65536      // 64 * 32 * 32 pixels
#define NELEM   4194304    // 64 * 64 * 32 * 32
#define QBLOCKS 16384      // NELEM / 256
#define CHUNK   64         // codes staged in smem per iteration

typedef unsigned long long u64;

// -------- device scratch (no allocations allowed) --------
__device__ float  g_codeS[NUM_EMB];
__device__ int    g_counts[NUM_EMB];
__device__ int    g_idx[NPIX];
__device__ double g_part[QBLOCKS];

// -------- packed f32x2 helpers (sm_100+) --------
__device__ __forceinline__ void fma2(u64& acc, u64 a, u64 b) {
    asm("fma.rn.f32x2 %0, %1, %2, %3;" : "=l"(acc) : "l"(a), "l"(b), "l"(acc));
}
__device__ __forceinline__ u64 add2(u64 a, u64 b) {
    u64 r; asm("add.rn.f32x2 %0, %1, %2;" : "=l"(r) : "l"(a), "l"(b)); return r;
}
__device__ __forceinline__ u64 pack2(float lo, float hi) {
    u64 r; asm("mov.b64 %0, {%1, %2};" : "=l"(r) : "f"(lo), "f"(hi)); return r;
}
__device__ __forceinline__ float2 unpack2(u64 v) {
    float lo, hi; asm("mov.b64 {%0, %1}, %2;" : "=f"(lo), "=f"(hi) : "l"(v));
    return make_float2(lo, hi);
}

// -------- kernel 1: code norms + zero histogram --------
__global__ void prep_kernel(const float* __restrict__ w) {
    int k = blockIdx.x * blockDim.x + threadIdx.x;
    if (k < NUM_EMB) {
        const float* row = w + k * EMB_DIM;
        float s = 0.0f;
        #pragma unroll
        for (int d = 0; d < EMB_DIM; d++)
            s = __fadd_rn(s, __fmul_rn(row[d], row[d]));
        g_codeS[k]  = s;
        g_counts[k] = 0;
    }
}

// -------- kernel 2: per-pixel argmin over 1024 codes --------
// dist_k = fl( fl(A + B_k) - m_k ),  m_k = sum_d (2*x_d)*e_kd  (matches reference formula)
__global__ void __launch_bounds__(256) argmin_kernel(const float* __restrict__ x,
                                                     const float* __restrict__ w,
                                                     float* __restrict__ out_idx) {
    __shared__ float sw[CHUNK * EMB_DIM];
    __shared__ float sS[CHUNK];

    int p  = blockIdx.x * 256 + threadIdx.x;       // pixel id: b*1024 + hw
    int b  = p >> 10;
    int hw = p & 1023;
    const float* xp = x + (size_t)b * 65536 + hw;  // NCHW: channel stride 1024

    // Load x into registers: A = ||x||^2 (sequential, like reference), x2 = packed 2*x
    u64 x2[32];
    float A = 0.0f;
    #pragma unroll
    for (int d = 0; d < EMB_DIM; d += 2) {
        float v0 = xp[(size_t)d * 1024];
        float v1 = xp[(size_t)(d + 1) * 1024];
        A = __fadd_rn(A, __fmul_rn(v0, v0));
        A = __fadd_rn(A, __fmul_rn(v1, v1));
        x2[d >> 1] = pack2(2.0f * v0, 2.0f * v1);  // *2 is exact
    }

    float best = 3.4e38f;
    int   bidx = 0;

    for (int k0 = 0; k0 < NUM_EMB; k0 += CHUNK) {
        __syncthreads();
        // stage CHUNK codes (4096 floats) into smem, coalesced float4 loads
        const float4* src = reinterpret_cast<const float4*>(w + k0 * EMB_DIM);
        float4*       dst = reinterpret_cast<float4*>(sw);
        #pragma unroll
        for (int t = 0; t < 4; t++)
            dst[threadIdx.x + 256 * t] = src[threadIdx.x + 256 * t];
        if (threadIdx.x < CHUNK) sS[threadIdx.x] = g_codeS[k0 + threadIdx.x];
        __syncthreads();

        for (int k = 0; k < CHUNK; k++) {
            const ulonglong2* e = reinterpret_cast<const ulonglong2*>(sw + k * EMB_DIM);
            u64 a0 = 0ull, a1 = 0ull, a2 = 0ull, a3 = 0ull;
            #pragma unroll
            for (int j = 0; j < 16; j += 2) {
                ulonglong2 e0 = e[j];         // LDS.128 (broadcast), 2 packed operands
                ulonglong2 e1 = e[j + 1];
                fma2(a0, x2[2 * j],     e0.x);
                fma2(a1, x2[2 * j + 1], e0.y);
                fma2(a2, x2[2 * j + 2], e1.x);
                fma2(a3, x2[2 * j + 3], e1.y);
            }
            float2 s = unpack2(add2(add2(a0, a1), add2(a2, a3)));
            float m  = __fadd_rn(s.x, s.y);
            float dist = __fsub_rn(__fadd_rn(A, sS[k]), m);
            if (dist < best) { best = dist; bidx = k0 + k; }   // first-index tie-break
        }
    }

    g_idx[p]   = bidx;
    out_idx[p] = (float)bidx;
    atomicAdd(&g_counts[bidx], 1);
}

// -------- kernel 3: quantized gather + straight-through output + loss partials --------
__global__ void __launch_bounds__(256) quant_kernel(const float* __restrict__ x,
                                                    const float* __restrict__ w,
                                                    float* __restrict__ out) {
    __shared__ double sred[256];
    int i  = blockIdx.x * 256 + threadIdx.x;   // over NELEM, NCHW order
    int b  = i >> 16;
    int c  = (i >> 10) & 63;
    int hw = i & 1023;

    int   idx = g_idx[b * 1024 + hw];
    float q   = w[idx * EMB_DIM + c];
    float xv  = x[i];
    // straight-through: x + (q - x), NOT just q (match reference rounding)
    out[i] = __fadd_rn(xv, __fsub_rn(q, xv));

    float  d  = __fsub_rn(q, xv);
    double dd = (double)d * (double)d;

    sred[threadIdx.x] = dd;
    __syncthreads();
    #pragma unroll
    for (int s = 128; s > 0; s >>= 1) {
        if (threadIdx.x < s) sred[threadIdx.x] += sred[threadIdx.x + s];
        __syncthreads();
    }
    if (threadIdx.x == 0) g_part[blockIdx.x] = sred[0];
}

// -------- kernel 4: deterministic final reduction: loss + perplexity --------
__global__ void __launch_bounds__(1024) final_kernel(float* __restrict__ out) {
    __shared__ double sd[1024];
    __shared__ float  sf[1024];
    int t = threadIdx.x;

    double s = 0.0;
    #pragma unroll
    for (int j = 0; j < QBLOCKS / 1024; j++)
        s += g_part[t * (QBLOCKS / 1024) + j];
    sd[t] = s;

    float cnt = (float)g_counts[t];
    float pr  = cnt * (1.0f / 65536.0f);
    sf[t] = pr * logf(pr + 1e-10f);           // 0 * log(eps) == 0, matches jnp
    __syncthreads();
    #pragma unroll
    for (int st = 512; st > 0; st >>= 1) {
        if (t < st) { sd[t] += sd[t + st]; sf[t] += sf[t + st]; }
        __syncthreads();
    }
    if (t == 0) {
        float m = (float)(sd[0] / (double)NELEM);       // mean((quantized - x)^2)
        out[NELEM]     = __fadd_rn(m, __fmul_rn(0.25f, m));  // q_loss + 0.25*e_loss
        out[NELEM + 1] = expf(-sf[0]);
    }
}

extern "C" void kernel_launch(void* const* d_in, const int* in_sizes, int n_in,
                              void* d_out, int out_size) {
    const float* x;
    const float* w;
    if (in_sizes[0] == NELEM) { x = (const float*)d_in[0]; w = (const float*)d_in[1]; }
    else                      { x = (const float*)d_in[1]; w = (const float*)d_in[0]; }
    float* out = (float*)d_out;

    prep_kernel<<<4, 256>>>(w);
    argmin_kernel<<<NPIX / 256, 256>>>(x, w, out + NELEM + 2);
    quant_kernel<<<NELEM / 256, 256>>>(x, w, out);
    final_kernel<<<1, 1024>>>(out);
}

// round 3
// speedup vs baseline: 1.7021x; 1.7021x over previous
#include <cuda_runtime.h>
#include <cuda_bf16.h>
#include <cstdint>

#define NUM_EMB 1024
#define EMB_DIM 64
#define NPIX    65536      // 64 * 32 * 32 pixels
#define NELEM   4194304    // 64 * 64 * 32 * 32
#define QB2     4096
#define CAP     32         // candidate buffer per pixel
#define DELTA   2e-4f      // screening window (>= 2*eps_gemm + grid slop)

// ---------------- device scratch (no allocs allowed) ----------------
__device__ float    g_codeS[NUM_EMB];
__device__ int      g_counts[NUM_EMB];
__device__ int      g_idx[NPIX];
__device__ double   g_part[QB2];
__device__ uint4    g_bfrag[128 * 4 * 32];        // [tile][group][lane] B fragments
__device__ int      g_cnt[NPIX];
__device__ unsigned short g_cidx[NPIX * CAP];
__device__ float    g_cd[NPIX * CAP];
__device__ float    g_best[NPIX];

// ---------------- helpers ----------------
static __device__ __forceinline__ float bfhi_f(float a) {
    return __bfloat162float(__float2bfloat16_rn(a));
}
static __device__ __forceinline__ uint32_t packbf(float a, float b) {
    uint16_t ha = __bfloat16_as_ushort(__float2bfloat16_rn(a));
    uint16_t hb = __bfloat16_as_ushort(__float2bfloat16_rn(b));
    return (uint32_t)ha | ((uint32_t)hb << 16);
}
static __device__ __forceinline__ uint32_t packlo(float a, float b) {
    return packbf(__fsub_rn(a, bfhi_f(a)), __fsub_rn(b, bfhi_f(b)));
}
static __device__ __forceinline__ void mma16816(float& c0, float& c1, float& c2, float& c3,
                                                uint32_t a0, uint32_t a1, uint32_t a2, uint32_t a3,
                                                uint32_t b0, uint32_t b1) {
    asm volatile("mma.sync.aligned.m16n8k16.row.col.f32.bf16.bf16.f32 "
                 "{%0,%1,%2,%3}, {%4,%5,%6,%7}, {%8,%9}, {%0,%1,%2,%3};"
                 : "+f"(c0), "+f"(c1), "+f"(c2), "+f"(c3)
                 : "r"(a0), "r"(a1), "r"(a2), "r"(a3), "r"(b0), "r"(b1));
}
static __device__ __forceinline__ void append_cand(int pix, int idx, float d) {
    int slot = atomicAdd(&g_cnt[pix], 1);
    if (slot < CAP) {
        g_cidx[pix * CAP + slot] = (unsigned short)idx;
        g_cd[pix * CAP + slot]   = d;
    }
}

// ---------------- kernel 1: code norms + fragment-ordered split-bf16 codebook ----------------
__global__ void __launch_bounds__(256) prep_kernel(const float* __restrict__ w) {
    int t = blockIdx.x * 256 + threadIdx.x;          // 4096 threads

    if (t < NUM_EMB) {                               // code norms (sequential, R1-validated)
        const float* row = w + t * EMB_DIM;
        float s = 0.0f;
        #pragma unroll
        for (int d = 0; d < EMB_DIM; d++)
            s = __fadd_rn(s, __fmul_rn(row[d], row[d]));
        g_codeS[t]  = s;
        g_counts[t] = 0;
    }

    // B fragments for mma.m16n8k16 (col-major B = codes):
    // b0 = {B[2q+16s][n], B[2q+1+16s][n]}, b1 = {B[2q+8+16s][n], B[2q+9+16s][n]}, n = lane/4
    int tile = t >> 5;
    int lane = t & 31;
    int n    = tile * 8 + (lane >> 2);
    int q    = lane & 3;
    const float* e = w + n * EMB_DIM;

    uint32_t hiw[8], low[8];
    #pragma unroll
    for (int s = 0; s < 4; s++) {
        int k0 = 16 * s + 2 * q;
        float a0 = e[k0],     a1 = e[k0 + 1];
        float b0 = e[k0 + 8], b1 = e[k0 + 9];
        hiw[2 * s]     = packbf(a0, a1);
        hiw[2 * s + 1] = packbf(b0, b1);
        low[2 * s]     = packlo(a0, a1);
        low[2 * s + 1] = packlo(b0, b1);
    }
    g_bfrag[tile * 128 +  0 + lane] = make_uint4(hiw[0], hiw[1], hiw[2], hiw[3]);
    g_bfrag[tile * 128 + 32 + lane] = make_uint4(hiw[4], hiw[5], hiw[6], hiw[7]);
    g_bfrag[tile * 128 + 64 + lane] = make_uint4(low[0], low[1], low[2], low[3]);
    g_bfrag[tile * 128 + 96 + lane] = make_uint4(low[4], low[5], low[6], low[7]);
}

// ---------------- kernel 2: HMMA split-bf16 screening (best + candidate windows) ----------------
__global__ void __launch_bounds__(128) argmin_kernel(const float* __restrict__ x) {
    __shared__ float sBN[NUM_EMB];
    int tid  = threadIdx.x;
    int warp = tid >> 5;
    int lane = tid & 31;
    int q    = lane & 3;
    int r    = lane >> 2;

    #pragma unroll
    for (int i = 0; i < 8; i++) sBN[tid + 128 * i] = g_codeS[tid + 128 * i];

    int p0b = blockIdx.x * 64;
    if (tid < 64) g_cnt[p0b + tid] = 0;
    __syncthreads();

    // ---- build A fragments (2x in split bf16) for this warp's 16 pixels ----
    int p0 = p0b + warp * 16;
    const float* xb = x + (size_t)(p0 >> 10) * 65536 + (p0 & 1023);  // NCHW, dim stride 1024

    uint32_t Ahi[16], Alo[16];
    #pragma unroll
    for (int s = 0; s < 4; s++) {
        int k0 = 16 * s + 2 * q;
        float p00 = 2.0f * xb[(size_t)k0 * 1024 + r];
        float p01 = 2.0f * xb[(size_t)(k0 + 1) * 1024 + r];
        float p10 = 2.0f * xb[(size_t)k0 * 1024 + r + 8];
        float p11 = 2.0f * xb[(size_t)(k0 + 1) * 1024 + r + 8];
        float p20 = 2.0f * xb[(size_t)(k0 + 8) * 1024 + r];
        float p21 = 2.0f * xb[(size_t)(k0 + 9) * 1024 + r];
        float p30 = 2.0f * xb[(size_t)(k0 + 8) * 1024 + r + 8];
        float p31 = 2.0f * xb[(size_t)(k0 + 9) * 1024 + r + 8];
        Ahi[s * 4 + 0] = packbf(p00, p01);  Alo[s * 4 + 0] = packlo(p00, p01);
        Ahi[s * 4 + 1] = packbf(p10, p11);  Alo[s * 4 + 1] = packlo(p10, p11);
        Ahi[s * 4 + 2] = packbf(p20, p21);  Alo[s * 4 + 2] = packlo(p20, p21);
        Ahi[s * 4 + 3] = packbf(p30, p31);  Alo[s * 4 + 3] = packlo(p30, p31);
    }

    float bestL = 3.4e38f, bestH = 3.4e38f;

    const uint4* bp = g_bfrag + lane;
    uint4 B0 = bp[0], B1 = bp[32], B2 = bp[64], B3 = bp[96];

    for (int t = 0; t < 128; t++) {
        uint4 N0, N1, N2, N3;
        if (t < 127) {
            const uint4* np = bp + (t + 1) * 128;
            N0 = np[0]; N1 = np[32]; N2 = np[64]; N3 = np[96];
        }
        float c0 = 0.f, c1 = 0.f, c2 = 0.f, c3 = 0.f;
        // hi * hi
        mma16816(c0, c1, c2, c3, Ahi[0],  Ahi[1],  Ahi[2],  Ahi[3],  B0.x, B0.y);
        mma16816(c0, c1, c2, c3, Ahi[4],  Ahi[5],  Ahi[6],  Ahi[7],  B0.z, B0.w);
        mma16816(c0, c1, c2, c3, Ahi[8],  Ahi[9],  Ahi[10], Ahi[11], B1.x, B1.y);
        mma16816(c0, c1, c2, c3, Ahi[12], Ahi[13], Ahi[14], Ahi[15], B1.z, B1.w);
        // hi * lo
        mma16816(c0, c1, c2, c3, Ahi[0],  Ahi[1],  Ahi[2],  Ahi[3],  B2.x, B2.y);
        mma16816(c0, c1, c2, c3, Ahi[4],  Ahi[5],  Ahi[6],  Ahi[7],  B2.z, B2.w);
        mma16816(c0, c1, c2, c3, Ahi[8],  Ahi[9],  Ahi[10], Ahi[11], B3.x, B3.y);
        mma16816(c0, c1, c2, c3, Ahi[12], Ahi[13], Ahi[14], Ahi[15], B3.z, B3.w);
        // lo * hi
        mma16816(c0, c1, c2, c3, Alo[0],  Alo[1],  Alo[2],  Alo[3],  B0.x, B0.y);
        mma16816(c0, c1, c2, c3, Alo[4],  Alo[5],  Alo[6],  Alo[7],  B0.z, B0.w);
        mma16816(c0, c1, c2, c3, Alo[8],  Alo[9],  Alo[10], Alo[11], B1.x, B1.y);
        mma16816(c0, c1, c2, c3, Alo[12], Alo[13], Alo[14], Alo[15], B1.z, B1.w);

        // epilogue: dist~ = ||e||^2 - m  (A-norm is constant per pixel, irrelevant for argmin)
        int n0 = t * 8 + 2 * q;
        float d0 = __fsub_rn(sBN[n0],     c0);
        float d1 = __fsub_rn(sBN[n0 + 1], c1);
        float d2 = __fsub_rn(sBN[n0],     c2);
        float d3 = __fsub_rn(sBN[n0 + 1], c3);

        bestL = fminf(bestL, fminf(d0, d1));
        bestH = fminf(bestH, fminf(d2, d3));
        // share best across the 4 lanes owning each row (subset-min stays sound)
        bestL = fminf(bestL, __shfl_xor_sync(0xFFFFFFFFu, bestL, 1));
        bestL = fminf(bestL, __shfl_xor_sync(0xFFFFFFFFu, bestL, 2));
        bestH = fminf(bestH, __shfl_xor_sync(0xFFFFFFFFu, bestH, 1));
        bestH = fminf(bestH, __shfl_xor_sync(0xFFFFFFFFu, bestH, 2));

        if (d0 < bestL + DELTA) append_cand(p0 + r,     n0,     d0);
        if (d1 < bestL + DELTA) append_cand(p0 + r,     n0 + 1, d1);
        if (d2 < bestH + DELTA) append_cand(p0 + r + 8, n0,     d2);
        if (d3 < bestH + DELTA) append_cand(p0 + r + 8, n0 + 1, d3);

        B0 = N0; B1 = N1; B2 = N2; B3 = N3;
    }

    if (q == 0) {
        g_best[p0 + r]     = bestL;
        g_best[p0 + r + 8] = bestH;
    }
}

// ---------------- kernel 3: exact fp32 rescore of candidates ----------------
__global__ void __launch_bounds__(128) rescore_kernel(const float* __restrict__ x,
                                                      const float* __restrict__ w,
                                                      float* __restrict__ out_idx) {
    int p = blockIdx.x * 128 + threadIdx.x;
    const float* xp = x + (size_t)(p >> 10) * 65536 + (p & 1023);

    float xv[EMB_DIM];
    float A = 0.0f;
    #pragma unroll
    for (int d = 0; d < EMB_DIM; d++) {
        float v = xp[(size_t)d * 1024];
        xv[d] = v;
        A = __fadd_rn(A, __fmul_rn(v, v));
    }

    int   cnt = g_cnt[p];
    float bb  = g_best[p] + DELTA;
    float bd  = 3.4e38f;
    int   bi  = 0;

    if (cnt > CAP) {                       // overflow fallback: exact full scan
        for (int k = 0; k < NUM_EMB; k++) {
            const float* e = w + k * EMB_DIM;
            float m = 0.0f;
            #pragma unroll
            for (int d = 0; d < EMB_DIM; d++) m = __fmaf_rn(xv[d], e[d], m);
            float dist = __fsub_rn(__fadd_rn(A, g_codeS[k]), 2.0f * m);
            if (dist < bd) { bd = dist; bi = k; }
        }
    } else {
        for (int j = 0; j < cnt; j++) {
            if (g_cd[p * CAP + j] > bb) continue;     // not within window of final best
            int k = g_cidx[p * CAP + j];
            const float* e = w + k * EMB_DIM;
            float m = 0.0f;
            #pragma unroll
            for (int d = 0; d < EMB_DIM; d++) m = __fmaf_rn(xv[d], e[d], m);
            float dist = __fsub_rn(__fadd_rn(A, g_codeS[k]), 2.0f * m);
            if (dist < bd || (dist == bd && k < bi)) { bd = dist; bi = k; }
        }
    }

    g_idx[p]   = bi;
    out_idx[p] = (float)bi;
    atomicAdd(&g_counts[bi], 1);
}

// ---------------- kernel 4: quantized gather + STE output + loss partials ----------------
__global__ void __launch_bounds__(256) quant_kernel(const float* __restrict__ x,
                                                    const float* __restrict__ w,
                                                    float* __restrict__ out) {
    __shared__ double sred[256];
    int t  = blockIdx.x * 256 + threadIdx.x;
    int i  = t * 4;
    int b  = i >> 16;
    int c  = (i >> 10) & 63;
    int hw = i & 1023;

    const int4   iv = *(const int4*)(g_idx + b * 1024 + hw);
    const float4 xv = *(const float4*)(x + i);

    float q0 = w[iv.x * EMB_DIM + c];
    float q1 = w[iv.y * EMB_DIM + c];
    float q2 = w[iv.z * EMB_DIM + c];
    float q3 = w[iv.w * EMB_DIM + c];

    float d0 = __fsub_rn(q0, xv.x), d1 = __fsub_rn(q1, xv.y);
    float d2 = __fsub_rn(q2, xv.z), d3 = __fsub_rn(q3, xv.w);

    float4 o;
    o.x = __fadd_rn(xv.x, d0); o.y = __fadd_rn(xv.y, d1);
    o.z = __fadd_rn(xv.z, d2); o.w = __fadd_rn(xv.w, d3);
    *(float4*)(out + i) = o;

    double dd = (double)d0 * d0 + (double)d1 * d1 + (double)d2 * d2 + (double)d3 * d3;
    sred[threadIdx.x] = dd;
    __syncthreads();
    #pragma unroll
    for (int s = 128; s > 0; s >>= 1) {
        if (threadIdx.x < s) sred[threadIdx.x] += sred[threadIdx.x + s];
        __syncthreads();
    }
    if (threadIdx.x == 0) g_part[blockIdx.x] = sred[0];
}

// ---------------- kernel 5: deterministic final reduction ----------------
__global__ void __launch_bounds__(1024) final_kernel(float* __restrict__ out) {
    __shared__ double sd[1024];
    __shared__ float  sf[1024];
    int t = threadIdx.x;

    double s = g_part[t * 4] + g_part[t * 4 + 1] + g_part[t * 4 + 2] + g_part[t * 4 + 3];
    sd[t] = s;

    float cnt = (float)g_counts[t];
    float pr  = cnt * (1.0f / 65536.0f);
    sf[t] = pr * logf(pr + 1e-10f);
    __syncthreads();
    #pragma unroll
    for (int st = 512; st > 0; st >>= 1) {
        if (t < st) { sd[t] += sd[t + st]; sf[t] += sf[t + st]; }
        __syncthreads();
    }
    if (t == 0) {
        float m = (float)(sd[0] / (double)NELEM);
        out[NELEM]     = __fadd_rn(m, __fmul_rn(0.25f, m));   // q_loss + 0.25*e_loss
        out[NELEM + 1] = expf(-sf[0]);
    }
}

extern "C" void kernel_launch(void* const* d_in, const int* in_sizes, int n_in,
                              void* d_out, int out_size) {
    const float* x;
    const float* w;
    if (in_sizes[0] == NELEM) { x = (const float*)d_in[0]; w = (const float*)d_in[1]; }
    else                      { x = (const float*)d_in[1]; w = (const float*)d_in[0]; }
    float* out = (float*)d_out;

    prep_kernel<<<16, 256>>>(w);
    argmin_kernel<<<NPIX / 64, 128>>>(x);
    rescore_kernel<<<NPIX / 128, 128>>>(x, w, out + NELEM + 2);
    quant_kernel<<<QB2, 256>>>(x, w, out);
    final_kernel<<<1, 1024>>>(out);
}

// round 4
// speedup vs baseline: 2.0891x; 1.2274x over previous
#include <cuda_runtime.h>
#include <cuda_bf16.h>
#include <cstdint>

#define NUM_EMB 1024
#define EMB_DIM 64
#define NPIX    65536      // 64 * 32 * 32 pixels
#define NELEM   4194304    // 64 * 64 * 32 * 32
#define NBLK    512        // finish-kernel blocks (128 px each)
#define CAP     32         // candidate buffer per pixel
#define DELTA   2e-3f      // screen window >= 2*max_gemm_err + grid slop

// ---------------- device scratch (no allocs allowed) ----------------
__device__ float    g_codeS[NUM_EMB];
__device__ int      g_counts[NUM_EMB];
__device__ double   g_part[NBLK];
__device__ int      g_ticket;
__device__ uint4    g_bfrag[128 * 64];            // [tile][group(2)x32 lanes] hi fragments
__device__ int      g_cnt[NPIX];
__device__ unsigned short g_cidx[NPIX * CAP];
__device__ float    g_cd[NPIX * CAP];
__device__ float    g_best[NPIX];

// ---------------- helpers ----------------
static __device__ __forceinline__ uint32_t packbf(float a, float b) {
    uint16_t ha = __bfloat16_as_ushort(__float2bfloat16_rn(a));
    uint16_t hb = __bfloat16_as_ushort(__float2bfloat16_rn(b));
    return (uint32_t)ha | ((uint32_t)hb << 16);
}
static __device__ __forceinline__ void mma16816(float& c0, float& c1, float& c2, float& c3,
                                                uint32_t a0, uint32_t a1, uint32_t a2, uint32_t a3,
                                                uint32_t b0, uint32_t b1) {
    asm volatile("mma.sync.aligned.m16n8k16.row.col.f32.bf16.bf16.f32 "
                 "{%0,%1,%2,%3}, {%4,%5,%6,%7}, {%8,%9}, {%0,%1,%2,%3};"
                 : "+f"(c0), "+f"(c1), "+f"(c2), "+f"(c3)
                 : "r"(a0), "r"(a1), "r"(a2), "r"(a3), "r"(b0), "r"(b1));
}
static __device__ __forceinline__ void append_cand(int pix, int idx, float d) {
    int slot = atomicAdd(&g_cnt[pix], 1);
    if (slot < CAP) {
        g_cidx[pix * CAP + slot] = (unsigned short)idx;
        g_cd[pix * CAP + slot]   = d;
    }
}

// ---------------- kernel 1: code norms + hi-bf16 fragment codebook + resets ----------------
__global__ void __launch_bounds__(256) prep_kernel(const float* __restrict__ w) {
    int t = blockIdx.x * 256 + threadIdx.x;          // 4096 threads

    if (t < NUM_EMB) {                               // exact code norms (R1-validated order)
        const float* row = w + t * EMB_DIM;
        float s = 0.0f;
        #pragma unroll
        for (int d = 0; d < EMB_DIM; d++)
            s = __fadd_rn(s, __fmul_rn(row[d], row[d]));
        g_codeS[t]  = s;
        g_counts[t] = 0;
    }
    if (t == 0) g_ticket = 0;

    // hi fragments for mma.m16n8k16, col-major B (codes): n = code row, q = lane&3
    int tile = t >> 5;
    int lane = t & 31;
    int n    = tile * 8 + (lane >> 2);
    int q    = lane & 3;
    const float* e = w + n * EMB_DIM;

    uint32_t hiw[8];
    #pragma unroll
    for (int s = 0; s < 4; s++) {
        int k0 = 16 * s + 2 * q;
        hiw[2 * s]     = packbf(e[k0],     e[k0 + 1]);
        hiw[2 * s + 1] = packbf(e[k0 + 8], e[k0 + 9]);
    }
    g_bfrag[tile * 64 +      lane] = make_uint4(hiw[0], hiw[1], hiw[2], hiw[3]);
    g_bfrag[tile * 64 + 32 + lane] = make_uint4(hiw[4], hiw[5], hiw[6], hiw[7]);
}

// ---------------- kernel 2: HMMA hi-bf16 screen, smem-shared B ----------------
__global__ void __launch_bounds__(256) argmin_kernel(const float* __restrict__ x) {
    __shared__ float sBN[NUM_EMB];
    __shared__ uint4 sB[2][1024];                    // 2 x 16KB: 16 tiles per stage

    int tid  = threadIdx.x;
    int warp = tid >> 5;
    int lane = tid & 31;
    int q    = lane & 3;
    int r    = lane >> 2;

    #pragma unroll
    for (int i = 0; i < 4; i++) sBN[tid + 256 * i] = g_codeS[tid + 256 * i];

    int p0b = blockIdx.x * 128;
    if (tid < 128) g_cnt[p0b + tid] = 0;

    // ---- A fragments (hi of 2x) for this warp's 16 pixels ----
    int p0 = p0b + warp * 16;
    const float* xb = x + (size_t)(p0 >> 10) * 65536 + (p0 & 1023);  // NCHW, dim stride 1024

    uint32_t Ahi[16];
    #pragma unroll
    for (int s = 0; s < 4; s++) {
        int k0 = 16 * s + 2 * q;
        float p00 = 2.0f * xb[(size_t)k0 * 1024 + r];
        float p01 = 2.0f * xb[(size_t)(k0 + 1) * 1024 + r];
        float p10 = 2.0f * xb[(size_t)k0 * 1024 + r + 8];
        float p11 = 2.0f * xb[(size_t)(k0 + 1) * 1024 + r + 8];
        float p20 = 2.0f * xb[(size_t)(k0 + 8) * 1024 + r];
        float p21 = 2.0f * xb[(size_t)(k0 + 9) * 1024 + r];
        float p30 = 2.0f * xb[(size_t)(k0 + 8) * 1024 + r + 8];
        float p31 = 2.0f * xb[(size_t)(k0 + 9) * 1024 + r + 8];
        Ahi[s * 4 + 0] = packbf(p00, p01);
        Ahi[s * 4 + 1] = packbf(p10, p11);
        Ahi[s * 4 + 2] = packbf(p20, p21);
        Ahi[s * 4 + 3] = packbf(p30, p31);
    }

    // prefetch stage 0
    #pragma unroll
    for (int i = 0; i < 4; i++) sB[0][tid + 256 * i] = g_bfrag[tid + 256 * i];
    __syncthreads();

    float bestL = 3.4e38f, bestH = 3.4e38f;

    for (int s = 0; s < 8; s++) {
        const uint4* cur = sB[s & 1];
        if (s < 7) {                                  // async-ish prefetch of next stage
            const uint4* src = g_bfrag + (s + 1) * 1024;
            uint4*       dst = sB[(s + 1) & 1];
            #pragma unroll
            for (int i = 0; i < 4; i++) dst[tid + 256 * i] = src[tid + 256 * i];
        }

        #pragma unroll
        for (int t = 0; t < 16; t++) {
            uint4 f0 = cur[t * 64 + lane];
            uint4 f1 = cur[t * 64 + 32 + lane];

            float c0 = 0.f, c1 = 0.f, c2 = 0.f, c3 = 0.f;
            mma16816(c0, c1, c2, c3, Ahi[0],  Ahi[1],  Ahi[2],  Ahi[3],  f0.x, f0.y);
            mma16816(c0, c1, c2, c3, Ahi[4],  Ahi[5],  Ahi[6],  Ahi[7],  f0.z, f0.w);
            mma16816(c0, c1, c2, c3, Ahi[8],  Ahi[9],  Ahi[10], Ahi[11], f1.x, f1.y);
            mma16816(c0, c1, c2, c3, Ahi[12], Ahi[13], Ahi[14], Ahi[15], f1.z, f1.w);

            int n0 = (s * 16 + t) * 8 + 2 * q;        // dist~ = ||e||^2 - m (A const/pixel)
            float d0 = __fsub_rn(sBN[n0],     c0);
            float d1 = __fsub_rn(sBN[n0 + 1], c1);
            float d2 = __fsub_rn(sBN[n0],     c2);
            float d3 = __fsub_rn(sBN[n0 + 1], c3);

            bestL = fminf(bestL, fminf(d0, d1));
            bestH = fminf(bestH, fminf(d2, d3));
            bestL = fminf(bestL, __shfl_xor_sync(0xFFFFFFFFu, bestL, 1));
            bestL = fminf(bestL, __shfl_xor_sync(0xFFFFFFFFu, bestL, 2));
            bestH = fminf(bestH, __shfl_xor_sync(0xFFFFFFFFu, bestH, 1));
            bestH = fminf(bestH, __shfl_xor_sync(0xFFFFFFFFu, bestH, 2));

            if (d0 < bestL + DELTA) append_cand(p0 + r,     n0,     d0);
            if (d1 < bestL + DELTA) append_cand(p0 + r,     n0 + 1, d1);
            if (d2 < bestH + DELTA) append_cand(p0 + r + 8, n0,     d2);
            if (d3 < bestH + DELTA) append_cand(p0 + r + 8, n0 + 1, d3);
        }
        __syncthreads();
    }

    if (q == 0) {
        g_best[p0 + r]     = bestL;
        g_best[p0 + r + 8] = bestH;
    }
}

// ---------------- kernel 3: fused exact rescore + quantize + STE + losses ----------------
__global__ void __launch_bounds__(128) finish_kernel(const float* __restrict__ x,
                                                     const float* __restrict__ w,
                                                     float* __restrict__ out) {
    __shared__ double sd[128];
    __shared__ float  sf[128];
    __shared__ bool   isLast;

    int tid = threadIdx.x;
    int p   = blockIdx.x * 128 + tid;
    int b   = p >> 10;
    int hw  = p & 1023;
    const float* xp = x + (size_t)b * 65536 + hw;

    // x row in registers + exact A
    float xv[EMB_DIM];
    float A = 0.0f;
    #pragma unroll
    for (int d = 0; d < EMB_DIM; d++) {
        float v = xp[(size_t)d * 1024];
        xv[d] = v;
        A = __fadd_rn(A, __fmul_rn(v, v));
    }

    // exact rescore of screened candidates
    int   cnt = g_cnt[p];
    float bb  = g_best[p] + DELTA;
    float bd  = 3.4e38f;
    int   bi  = 0;

    if (cnt > CAP) {                                  // overflow: exact full scan
        for (int k = 0; k < NUM_EMB; k++) {
            const float* e = w + k * EMB_DIM;
            float m = 0.0f;
            #pragma unroll
            for (int d = 0; d < EMB_DIM; d++) m = __fmaf_rn(xv[d], e[d], m);
            float dist = __fsub_rn(__fadd_rn(A, g_codeS[k]), 2.0f * m);
            if (dist < bd) { bd = dist; bi = k; }
        }
    } else {
        for (int j = 0; j < cnt; j++) {
            if (g_cd[p * CAP + j] > bb) continue;
            int k = g_cidx[p * CAP + j];
            const float* e = w + k * EMB_DIM;
            float m = 0.0f;
            #pragma unroll
            for (int d = 0; d < EMB_DIM; d++) m = __fmaf_rn(xv[d], e[d], m);
            float dist = __fsub_rn(__fadd_rn(A, g_codeS[k]), 2.0f * m);
            if (dist < bd || (dist == bd && k < bi)) { bd = dist; bi = k; }
        }
    }

    out[NELEM + 2 + p] = (float)bi;                   // idx output
    atomicAdd(&g_counts[bi], 1);

    // quantize + straight-through + loss partial (row gather via LDG.128)
    const float4* wr = reinterpret_cast<const float4*>(w + bi * EMB_DIM);
    float* ob = out + (size_t)b * 65536 + hw;
    double acc = 0.0;
    #pragma unroll
    for (int j = 0; j < 16; j++) {
        float4 qv = wr[j];
        float x0 = xv[4 * j], x1 = xv[4 * j + 1], x2 = xv[4 * j + 2], x3 = xv[4 * j + 3];
        float d0 = __fsub_rn(qv.x, x0), d1 = __fsub_rn(qv.y, x1);
        float d2 = __fsub_rn(qv.z, x2), d3 = __fsub_rn(qv.w, x3);
        ob[(size_t)(4 * j)     * 1024] = __fadd_rn(x0, d0);
        ob[(size_t)(4 * j + 1) * 1024] = __fadd_rn(x1, d1);
        ob[(size_t)(4 * j + 2) * 1024] = __fadd_rn(x2, d2);
        ob[(size_t)(4 * j + 3) * 1024] = __fadd_rn(x3, d3);
        acc += (double)d0 * d0 + (double)d1 * d1 + (double)d2 * d2 + (double)d3 * d3;
    }

    sd[tid] = acc;
    __syncthreads();
    #pragma unroll
    for (int s = 64; s > 0; s >>= 1) {
        if (tid < s) sd[tid] += sd[tid + s];
        __syncthreads();
    }
    if (tid == 0) g_part[blockIdx.x] = sd[0];
    __threadfence();
    if (tid == 0) isLast = (atomicAdd(&g_ticket, 1) == NBLK - 1);
    __syncthreads();

    if (isLast) {                                     // deterministic final reduction
        __threadfence();
        double s = 0.0;
        #pragma unroll
        for (int i = 0; i < NBLK / 128; i++) s += g_part[tid * (NBLK / 128) + i];
        sd[tid] = s;

        float f = 0.0f;
        #pragma unroll
        for (int i = 0; i < NUM_EMB / 128; i++) {
            float pr = (float)g_counts[tid * (NUM_EMB / 128) + i] * (1.0f / 65536.0f);
            f += pr * logf(pr + 1e-10f);
        }
        sf[tid] = f;
        __syncthreads();
        #pragma unroll
        for (int st = 64; st > 0; st >>= 1) {
            if (tid < st) { sd[tid] += sd[tid + st]; sf[tid] += sf[tid + st]; }
            __syncthreads();
        }
        if (tid == 0) {
            float m = (float)(sd[0] / (double)NELEM);
            out[NELEM]     = __fadd_rn(m, __fmul_rn(0.25f, m));  // q_loss + 0.25*e_loss
            out[NELEM + 1] = expf(-sf[0]);
        }
    }
}

extern "C" void kernel_launch(void* const* d_in, const int* in_sizes, int n_in,
                              void* d_out, int out_size) {
    const float* x;
    const float* w;
    if (in_sizes[0] == NELEM) { x = (const float*)d_in[0]; w = (const float*)d_in[1]; }
    else                      { x = (const float*)d_in[1]; w = (const float*)d_in[0]; }
    float* out = (float*)d_out;

    prep_kernel<<<16, 256>>>(w);
    argmin_kernel<<<NPIX / 128, 256>>>(x);
    finish_kernel<<<NBLK, 128>>>(x, w, out);
}